// round 9
// baseline (speedup 1.0000x reference)
#include <cuda_runtime.h>
#include <stdint.h>

// TestSpatialTransform == two center crops:
//   out[0:N)   = data[:, :, 16:176, 16:176, 16:176]
//   out[N:2N)  = seg [:, :, 16:176, 16:176, 16:176]
// Pure HBM copy at minimum traffic (524 MB). Optimal shape from 8-round sweep:
// MLP=2 per thread (data+seg at same crop index), one float4 per thread,
// lane-contiguous warps, 256-thread blocks, one-shot, exact grid.
// This round: streaming loads (.cs, zero reuse) but DEFAULT stores — let the
// 126 MB L2 buffer dirty output lines and write back in large bursts,
// reducing DRAM read/write bus turnaround.

#define PATCH 160
#define SRC   192
#define OFF   16
#define W4    (PATCH / 4)              // 40 float4 per row
#define N_F4_PER_TENSOR (8 * PATCH * PATCH * W4)   // 8,192,000 = 32000*256 exact

__global__ void __launch_bounds__(256)
crop_copy2c_kernel(const float* __restrict__ data,
                   const float* __restrict__ seg,
                   float4* __restrict__ out)
{
    int idx = blockIdx.x * blockDim.x + threadIdx.x;   // exact grid, no tail

    int w4 = idx % W4;
    int t  = idx / W4;
    int h  = t % PATCH; t /= PATCH;
    int d  = t % PATCH;
    int bc = t / PATCH;

    // source flat float index within (8, 192, 192, 192)
    int sidx = (((bc * SRC) + (d + OFF)) * SRC + (h + OFF)) * SRC + OFF + (w4 << 2);

    // streaming loads (no reuse), default stores (L2 write-burst buffering)
    float4 a = __ldcs(reinterpret_cast<const float4*>(data + sidx));
    float4 b = __ldcs(reinterpret_cast<const float4*>(seg  + sidx));

    out[idx] = a;
    out[idx + N_F4_PER_TENSOR] = b;
}

extern "C" void kernel_launch(void* const* d_in, const int* in_sizes, int n_in,
                              void* d_out, int out_size)
{
    const float* data = (const float*)d_in[0];
    const float* seg  = (const float*)d_in[1];
    float4* out = (float4*)d_out;

    const int threads = 256;
    const int blocks  = N_F4_PER_TENSOR / threads;   // 32000 exactly
    crop_copy2c_kernel<<<blocks, threads>>>(data, seg, out);
}

// round 10
// speedup vs baseline: 1.0178x; 1.0178x over previous
#include <cuda_runtime.h>
#include <stdint.h>

// TestSpatialTransform_19095424598596 — FINAL.
//
// The reference's trilinear spatial transform collapses exactly:
//   coords = arange(160) - 79.5 + 95.5 = arange(160) + 16  -> integer coords
//   => map_coordinates(order=1) is an identity gather = center crop.
//   out[0:N)  = data[:, :, 16:176, 16:176, 16:176]
//   out[N:2N) = seg [:, :, 16:176, 16:176, 16:176]
//
// Pure HBM copy at provably minimal traffic (524 MB: 262 read + 262 write,
// zero sector overfetch — every 640 B source row starts 64 B-aligned).
//
// Converged optimum from a 9-round sweep (MLP 1/2/4/16, block 256/512,
// thread-contig vs lane-contig, bc-spread, sw-pipeline, persistent loop,
// .cs vs default stores): MLP=2 per thread (data+seg at the same crop
// index), one float4 per thread, lane-contiguous warps (512 B/warp/tensor),
// 256-thread blocks, one-shot, exact grid. 6.6 TB/s sustained = the HBM3e
// mixed read/write stream ceiling on this part; every deviation regressed.

#define PATCH 160
#define SRC   192
#define OFF   16
#define W4    (PATCH / 4)              // 40 float4 per row
#define N_F4_PER_TENSOR (8 * PATCH * PATCH * W4)   // 8,192,000 = 32000*256 exact

__global__ void __launch_bounds__(256)
crop_copy_final_kernel(const float* __restrict__ data,
                       const float* __restrict__ seg,
                       float4* __restrict__ out)
{
    int idx = blockIdx.x * blockDim.x + threadIdx.x;   // exact grid, no tail

    int w4 = idx % W4;
    int t  = idx / W4;
    int h  = t % PATCH; t /= PATCH;
    int d  = t % PATCH;
    int bc = t / PATCH;

    // source flat float index within (8, 192, 192, 192)
    int sidx = (((bc * SRC) + (d + OFF)) * SRC + (h + OFF)) * SRC + OFF + (w4 << 2);

    // two independent streaming loads, then two coalesced streaming stores
    float4 a = __ldcs(reinterpret_cast<const float4*>(data + sidx));
    float4 b = __ldcs(reinterpret_cast<const float4*>(seg  + sidx));

    __stcs(out + idx, a);
    __stcs(out + idx + N_F4_PER_TENSOR, b);
}

extern "C" void kernel_launch(void* const* d_in, const int* in_sizes, int n_in,
                              void* d_out, int out_size)
{
    const float* data = (const float*)d_in[0];
    const float* seg  = (const float*)d_in[1];
    float4* out = (float4*)d_out;

    const int threads = 256;
    const int blocks  = N_F4_PER_TENSOR / threads;   // 32000 exactly
    crop_copy_final_kernel<<<blocks, threads>>>(data, seg, out);
}

// round 11
// speedup vs baseline: 1.0325x; 1.0144x over previous
#include <cuda_runtime.h>
#include <stdint.h>

// TestSpatialTransform_19095424598596 — converged optimum (locked).
//
// The trilinear spatial transform collapses exactly: the sampling coords are
// arange(160) - 79.5 + 95.5 = arange(160) + 16 (integers), so order-1
// map_coordinates is an identity gather = center crop:
//   out[0:N)  = data[:, :, 16:176, 16:176, 16:176]
//   out[N:2N) = seg [:, :, 16:176, 16:176, 16:176]
//
// Pure HBM copy at provably minimal traffic (524 MB; every 640 B source row
// is 32 B-sector exact — zero overfetch). 10-round sweep over MLP {1,2,4,16},
// block {256,512}, thread- vs lane-contiguity, bc-spread, software pipelining,
// persistent loops, and cache policies all converge to ~6.6 TB/s = the HBM3e
// mixed read/write stream ceiling on this part (~83% of 8 TB/s spec).
// Best-benched configuration: MLP=2 per thread (data+seg at the same crop
// index), one float4 per thread, lane-contiguous warps, 512-thread blocks,
// exact grid, streaming loads and stores.

#define PATCH 160
#define SRC   192
#define OFF   16
#define W4    (PATCH / 4)              // 40 float4 per row
#define N_F4_PER_TENSOR (8 * PATCH * PATCH * W4)   // 8,192,000 = 16000*512 exact

__global__ void __launch_bounds__(512)
crop_copy_locked_kernel(const float* __restrict__ data,
                        const float* __restrict__ seg,
                        float4* __restrict__ out)
{
    int idx = blockIdx.x * blockDim.x + threadIdx.x;   // exact grid, no tail

    int w4 = idx % W4;
    int t  = idx / W4;
    int h  = t % PATCH; t /= PATCH;
    int d  = t % PATCH;
    int bc = t / PATCH;

    // source flat float index within (8, 192, 192, 192)
    int sidx = (((bc * SRC) + (d + OFF)) * SRC + (h + OFF)) * SRC + OFF + (w4 << 2);

    // two independent streaming loads, two coalesced streaming stores
    float4 a = __ldcs(reinterpret_cast<const float4*>(data + sidx));
    float4 b = __ldcs(reinterpret_cast<const float4*>(seg  + sidx));

    __stcs(out + idx, a);
    __stcs(out + idx + N_F4_PER_TENSOR, b);
}

extern "C" void kernel_launch(void* const* d_in, const int* in_sizes, int n_in,
                              void* d_out, int out_size)
{
    const float* data = (const float*)d_in[0];
    const float* seg  = (const float*)d_in[1];
    float4* out = (float4*)d_out;

    const int threads = 512;
    const int blocks  = N_F4_PER_TENSOR / threads;   // 16000 exactly
    crop_copy_locked_kernel<<<blocks, threads>>>(data, seg, out);
}